// round 3
// baseline (speedup 1.0000x reference)
#include <cuda_runtime.h>
#include <math.h>

// Problem constants
#define DD 300
#define HH 4
#define HD 1200           // H*D
#define MAXN 50000
#define MAXE 200000

// ---------------- scratch (static device globals; no allocation) ----------------
__device__ __align__(16) float g_fsrc [(size_t)MAXN * HD];   // [N,H,D] = feat @ Wg
__device__ __align__(16) float g_el   [MAXN * HH];
__device__ __align__(16) float g_er   [MAXN * HH];
__device__ __align__(16) float g_neigh[(size_t)MAXN * DD];   // SAGE h_neigh
__device__ __align__(16) float g_sage [(size_t)MAXN * DD];
__device__ int g_cntg[MAXN], g_cnt1[MAXN];
__device__ int g_curg[MAXN], g_cur1[MAXN];
__device__ int g_offsg[MAXN + 1], g_offs1[MAXN + 1];
__device__ int g_adjg[MAXE], g_adj1[MAXE];

__device__ __forceinline__ unsigned f2tf32(float x) {
    unsigned r;
    asm("cvt.rna.tf32.f32 %0, %1;" : "=r"(r) : "f"(x));
    return r;
}

// ================= TF32 tensor-core GEMM (double-buffered) =================
// C[M,Ncol] = A[M,K] @ B[K,Ncol] (+bias)
// Block 128x64, BK=16, 256 threads (8 warps as 4m x 2n), warp tile 32x32.
// SMEM in per-mma-fragment order so mainloop uses LDS.128/LDS.64.
#define GBM 128
#define GBN 64
#define GBK 16

__global__ __launch_bounds__(256) void gemm_tf32_kernel(
    const float* __restrict__ A, const float* __restrict__ B, float* __restrict__ C,
    int M, int Ncol, int K, const float* __restrict__ bias)
{
    __shared__ unsigned As[2][8 * 2 * 32 * 4];
    __shared__ unsigned Bs[2][8 * 2 * 32 * 2];

    const int tid  = threadIdx.x;
    const int lane = tid & 31;
    const int wid  = tid >> 5;
    const int wm   = wid & 3;
    const int wn   = wid >> 2;
    const int rowBase = blockIdx.y * GBM;
    const int colBase = blockIdx.x * GBN;

    float acc[2][4][4];
    #pragma unroll
    for (int i = 0; i < 2; i++)
        #pragma unroll
        for (int j = 0; j < 4; j++)
            #pragma unroll
            for (int r = 0; r < 4; r++) acc[i][j][r] = 0.f;

    float4 ra[2];
    float4 rb;

    const int a_r0 = (tid) >> 2,        a_c4_0 = (tid) & 3;
    const int a_r1 = (tid + 256) >> 2,  a_c4_1 = (tid + 256) & 3;
    const int b_r  = tid >> 4,          b_c4   = tid & 15;

    auto loadG = [&](int kt) {
        {
            int gr = rowBase + a_r0, gc = kt + a_c4_0 * 4;
            float4 v = make_float4(0.f, 0.f, 0.f, 0.f);
            if (gr < M && gc < K) v = *(const float4*)(A + (size_t)gr * K + gc);
            ra[0] = v;
        }
        {
            int gr = rowBase + a_r1, gc = kt + a_c4_1 * 4;
            float4 v = make_float4(0.f, 0.f, 0.f, 0.f);
            if (gr < M && gc < K) v = *(const float4*)(A + (size_t)gr * K + gc);
            ra[1] = v;
        }
        {
            int grow = kt + b_r, gc = colBase + b_c4 * 4;
            float4 v = make_float4(0.f, 0.f, 0.f, 0.f);
            if (grow < K && gc < Ncol)
                v = *(const float4*)(B + (size_t)grow * Ncol + gc);
            rb = v;
        }
    };

    auto storeS = [&](int buf) {
        #pragma unroll
        for (int q = 0; q < 2; q++) {
            int r  = q ? a_r1 : a_r0;
            int c4 = q ? a_c4_1 : a_c4_0;
            float vv[4] = {q ? ra[1].x : ra[0].x, q ? ra[1].y : ra[0].y,
                           q ? ra[1].z : ra[0].z, q ? ra[1].w : ra[0].w};
            int mt = r >> 4, rl = r & 15;
            int g = rl & 7, hi = rl >> 3;
            #pragma unroll
            for (int j = 0; j < 4; j++) {
                int c = c4 * 4 + j;
                int ks = c >> 3, cl = c & 7;
                int tig = cl & 3, chi = cl >> 2;
                int slane = g * 4 + tig;
                int jj = hi + 2 * chi;
                As[buf][(((mt * 2 + ks) * 32) + slane) * 4 + jj] = f2tf32(vv[j]);
            }
        }
        {
            float vv[4] = {rb.x, rb.y, rb.z, rb.w};
            int ks = b_r >> 3, kl = b_r & 7;
            int tig = kl & 3, jj = kl >> 2;
            #pragma unroll
            for (int j = 0; j < 4; j++) {
                int c = b_c4 * 4 + j;
                int nt = c >> 3, nl = c & 7;
                int slane = nl * 4 + tig;
                Bs[buf][(((nt * 2 + ks) * 32) + slane) * 2 + jj] = f2tf32(vv[j]);
            }
        }
    };

    const int KITERS = (K + GBK - 1) / GBK;
    loadG(0);
    storeS(0);
    __syncthreads();

    for (int it = 0; it < KITERS; it++) {
        int cur = it & 1;
        if (it + 1 < KITERS) loadG((it + 1) * GBK);

        #pragma unroll
        for (int ks = 0; ks < 2; ks++) {
            uint4 af[2];
            #pragma unroll
            for (int i = 0; i < 2; i++) {
                int mt = wm * 2 + i;
                af[i] = *(const uint4*)&As[cur][(((mt * 2 + ks) * 32) + lane) * 4];
            }
            uint2 bf[4];
            #pragma unroll
            for (int j = 0; j < 4; j++) {
                int nt = wn * 4 + j;
                bf[j] = *(const uint2*)&Bs[cur][(((nt * 2 + ks) * 32) + lane) * 2];
            }
            #pragma unroll
            for (int i = 0; i < 2; i++)
                #pragma unroll
                for (int j = 0; j < 4; j++) {
                    asm volatile(
                        "mma.sync.aligned.m16n8k8.row.col.f32.tf32.tf32.f32 "
                        "{%0,%1,%2,%3}, {%4,%5,%6,%7}, {%8,%9}, {%0,%1,%2,%3};"
                        : "+f"(acc[i][j][0]), "+f"(acc[i][j][1]),
                          "+f"(acc[i][j][2]), "+f"(acc[i][j][3])
                        : "r"(af[i].x), "r"(af[i].y), "r"(af[i].z), "r"(af[i].w),
                          "r"(bf[j].x), "r"(bf[j].y));
                }
        }

        if (it + 1 < KITERS) {
            storeS((it + 1) & 1);
            __syncthreads();
        }
    }

    const int g   = lane >> 2;
    const int tig = lane & 3;
    #pragma unroll
    for (int i = 0; i < 2; i++) {
        int grow0 = rowBase + (wm * 2 + i) * 16 + g;
        #pragma unroll
        for (int j = 0; j < 4; j++) {
            int gcol = colBase + (wn * 4 + j) * 8 + tig * 2;
            if (gcol >= Ncol) continue;
            float b0 = 0.f, b1 = 0.f;
            if (bias) { b0 = bias[gcol]; b1 = bias[gcol + 1]; }
            if (grow0 < M) {
                float2 v = make_float2(acc[i][j][0] + b0, acc[i][j][1] + b1);
                *(float2*)(C + (size_t)grow0 * Ncol + gcol) = v;
            }
            if (grow0 + 8 < M) {
                float2 v = make_float2(acc[i][j][2] + b0, acc[i][j][3] + b1);
                *(float2*)(C + (size_t)(grow0 + 8) * Ncol + gcol) = v;
            }
        }
    }
}

// ---------------- CSR build: histogram, scan, scatter ----------------
__global__ void hist_kernel(const int* __restrict__ dst, const int* __restrict__ dst1,
                            int* __restrict__ cntg, int* __restrict__ cnt1, int E)
{
    int i = blockIdx.x * blockDim.x + threadIdx.x;
    if (i >= E) return;
    atomicAdd(&cntg[dst[i]], 1);
    atomicAdd(&cnt1[dst1[i]], 1);
}

// one block per array (blockIdx 0 -> graph g, 1 -> graph g1), 1024 threads
__global__ void scan2_kernel(const int* __restrict__ cntg, const int* __restrict__ cnt1,
                             int* __restrict__ offsg, int* __restrict__ offs1, int n)
{
    const int* cnt = blockIdx.x ? cnt1 : cntg;
    int* offs = blockIdx.x ? offs1 : offsg;
    __shared__ int part[1024];
    int t = threadIdx.x;
    int chunk = (n + 1023) >> 10;
    int b = t * chunk;
    int e = min(b + chunk, n);
    int s = 0;
    for (int i = b; i < e; i++) s += cnt[i];
    part[t] = s;
    __syncthreads();
    for (int o = 1; o < 1024; o <<= 1) {
        int v = (t >= o) ? part[t - o] : 0;
        __syncthreads();
        part[t] += v;
        __syncthreads();
    }
    int ex = t ? part[t - 1] : 0;
    for (int i = b; i < e; i++) { offs[i] = ex; ex += cnt[i]; }
    if (t == 1023) offs[n] = ex;
}

__global__ void scatter_kernel(const int* __restrict__ src, const int* __restrict__ dst,
                               const int* __restrict__ src1, const int* __restrict__ dst1,
                               const int* __restrict__ offsg, const int* __restrict__ offs1,
                               int* __restrict__ curg, int* __restrict__ cur1,
                               int* __restrict__ adjg, int* __restrict__ adj1, int E)
{
    int i = blockIdx.x * blockDim.x + threadIdx.x;
    if (i >= E) return;
    int d = dst[i];
    adjg[offsg[d] + atomicAdd(&curg[d], 1)] = src[i];
    int d1 = dst1[i];
    adj1[offs1[d1] + atomicAdd(&cur1[d1], 1)] = src1[i];
}

// ---------------- el/er: per-(node,head) dot with attn_l / attn_r ----------------
__global__ void el_er_kernel(const float* __restrict__ fsrc,
                             const float* __restrict__ attn_l,
                             const float* __restrict__ attn_r,
                             float* __restrict__ el, float* __restrict__ er)
{
    int n = blockIdx.x;
    int w = threadIdx.x >> 5;
    int lane = threadIdx.x & 31;
    const float* fr = fsrc + (size_t)n * HD + w * DD;
    const float* al = attn_l + w * DD;
    const float* ar = attn_r + w * DD;
    float sl = 0.f, sr = 0.f;
    for (int d = lane; d < DD; d += 32) {
        float f = fr[d];
        sl += f * al[d];
        sr += f * ar[d];
    }
    #pragma unroll
    for (int o = 16; o; o >>= 1) {
        sl += __shfl_down_sync(0xffffffffu, sl, o);
        sr += __shfl_down_sync(0xffffffffu, sr, o);
    }
    if (lane == 0) {
        el[n * HH + w] = sl;
        er[n * HH + w] = sr;
    }
}

// ---------------- SAGE gcn-mean over CSR: warp per node ----------------
__global__ void sage_neigh_kernel(const float* __restrict__ feat,
                                  const int* __restrict__ offs1,
                                  const int* __restrict__ adj1,
                                  float* __restrict__ hneigh, int N)
{
    int n = (blockIdx.x * blockDim.x + threadIdx.x) >> 5;
    int lane = threadIdx.x & 31;
    if (n >= N) return;
    int beg = offs1[n], end = offs1[n + 1];
    float deg = (float)(end - beg);
    const float4* self = (const float4*)(feat + (size_t)n * DD);
    float4 acc[3];
    #pragma unroll
    for (int k = 0; k < 3; k++) {
        int idx = lane + 32 * k;
        if (idx < 75) acc[k] = self[idx];
    }
    for (int e = beg; e < end; e++) {
        int s = adj1[e];
        const float4* fr = (const float4*)(feat + (size_t)s * DD);
        #pragma unroll
        for (int k = 0; k < 3; k++) {
            int idx = lane + 32 * k;
            if (idx < 75) {
                float4 v = fr[idx];
                acc[k].x += v.x; acc[k].y += v.y; acc[k].z += v.z; acc[k].w += v.w;
            }
        }
    }
    float sc = 1.0f / (deg + 1.0f);
    float4* outp = (float4*)(hneigh + (size_t)n * DD);
    #pragma unroll
    for (int k = 0; k < 3; k++) {
        int idx = lane + 32 * k;
        if (idx < 75) {
            acc[k].x *= sc; acc[k].y *= sc; acc[k].z *= sc; acc[k].w *= sc;
            outp[idx] = acc[k];
        }
    }
}

// ---------------- fused GAT softmax + aggregation + gating + residual ----------------
// block per dst node, 256 threads
__global__ __launch_bounds__(256) void gat_final_kernel(
    const float* __restrict__ fsrc,
    const float* __restrict__ el, const float* __restrict__ er,
    const int* __restrict__ offs, const int* __restrict__ adj,
    const float* __restrict__ sage, const float* __restrict__ feat,
    const float* __restrict__ b_gat,
    const float* __restrict__ Whw, const float* __restrict__ bhw,
    float* __restrict__ out, int N)
{
    int n = blockIdx.x;
    int t = threadIdx.x;
    int lane = t & 31;
    int wid = t >> 5;

    __shared__ int   s_src[32];
    __shared__ float s_alpha[32][4];
    __shared__ float att[1500];     // [4 heads x 300] gat, [300] sage
    __shared__ float sw[5];

    int beg = offs[n], end = offs[n + 1];
    int deg = end - beg;

    // warp 0: softmax stats (kept in registers; all lanes hold reduced values)
    float m0 = -INFINITY, m1 = -INFINITY, m2 = -INFINITY, m3 = -INFINITY;
    float z0 = 0.f, z1 = 0.f, z2 = 0.f, z3 = 0.f;
    float4 rr;
    if (wid == 0) {
        rr = ((const float4*)er)[n];
        for (int i = lane; i < deg; i += 32) {
            int s = adj[beg + i];
            float4 l = ((const float4*)el)[s];
            float e0 = l.x + rr.x; e0 = e0 > 0.f ? e0 : 0.2f * e0;
            float e1 = l.y + rr.y; e1 = e1 > 0.f ? e1 : 0.2f * e1;
            float e2 = l.z + rr.z; e2 = e2 > 0.f ? e2 : 0.2f * e2;
            float e3 = l.w + rr.w; e3 = e3 > 0.f ? e3 : 0.2f * e3;
            m0 = fmaxf(m0, e0); m1 = fmaxf(m1, e1);
            m2 = fmaxf(m2, e2); m3 = fmaxf(m3, e3);
        }
        #pragma unroll
        for (int o = 16; o; o >>= 1) {
            m0 = fmaxf(m0, __shfl_xor_sync(0xffffffffu, m0, o));
            m1 = fmaxf(m1, __shfl_xor_sync(0xffffffffu, m1, o));
            m2 = fmaxf(m2, __shfl_xor_sync(0xffffffffu, m2, o));
            m3 = fmaxf(m3, __shfl_xor_sync(0xffffffffu, m3, o));
        }
        for (int i = lane; i < deg; i += 32) {
            int s = adj[beg + i];
            float4 l = ((const float4*)el)[s];
            float e0 = l.x + rr.x; e0 = e0 > 0.f ? e0 : 0.2f * e0;
            float e1 = l.y + rr.y; e1 = e1 > 0.f ? e1 : 0.2f * e1;
            float e2 = l.z + rr.z; e2 = e2 > 0.f ? e2 : 0.2f * e2;
            float e3 = l.w + rr.w; e3 = e3 > 0.f ? e3 : 0.2f * e3;
            z0 += expf(e0 - m0); z1 += expf(e1 - m1);
            z2 += expf(e2 - m2); z3 += expf(e3 - m3);
        }
        #pragma unroll
        for (int o = 16; o; o >>= 1) {
            z0 += __shfl_xor_sync(0xffffffffu, z0, o);
            z1 += __shfl_xor_sync(0xffffffffu, z1, o);
            z2 += __shfl_xor_sync(0xffffffffu, z2, o);
            z3 += __shfl_xor_sync(0xffffffffu, z3, o);
        }
    }

    float acc[5] = {0.f, 0.f, 0.f, 0.f, 0.f};
    int head_k[5];
    #pragma unroll
    for (int k = 0; k < 5; k++) head_k[k] = (t + 256 * k) / DD;

    for (int c = 0; c < deg; c += 32) {
        int cn = min(32, deg - c);
        __syncthreads();
        if (wid == 0 && lane < cn) {
            int s = adj[beg + c + lane];
            s_src[lane] = s;
            float4 l = ((const float4*)el)[s];
            float e0 = l.x + rr.x; e0 = e0 > 0.f ? e0 : 0.2f * e0;
            float e1 = l.y + rr.y; e1 = e1 > 0.f ? e1 : 0.2f * e1;
            float e2 = l.z + rr.z; e2 = e2 > 0.f ? e2 : 0.2f * e2;
            float e3 = l.w + rr.w; e3 = e3 > 0.f ? e3 : 0.2f * e3;
            s_alpha[lane][0] = expf(e0 - m0) / z0;
            s_alpha[lane][1] = expf(e1 - m1) / z1;
            s_alpha[lane][2] = expf(e2 - m2) / z2;
            s_alpha[lane][3] = expf(e3 - m3) / z3;
        }
        __syncthreads();
        for (int j = 0; j < cn; j++) {
            int s = s_src[j];
            const float* fr = fsrc + (size_t)s * HD;
            float a[4] = {s_alpha[j][0], s_alpha[j][1], s_alpha[j][2], s_alpha[j][3]};
            #pragma unroll
            for (int k = 0; k < 5; k++) {
                int idx = t + 256 * k;
                if (idx < HD) acc[k] += a[head_k[k]] * fr[idx];
            }
        }
    }
    __syncthreads();

    // stage att rows: gat heads + b_gat, then sage row
    #pragma unroll
    for (int k = 0; k < 5; k++) {
        int idx = t + 256 * k;
        if (idx < HD) att[idx] = acc[k] + b_gat[idx];
    }
    #pragma unroll
    for (int k = 0; k < 2; k++) {
        int dI = t + 256 * k;
        if (dI < DD) att[HD + dI] = sage[(size_t)n * DD + dI];
    }
    __syncthreads();

    // gating: warp r computes sigmoid(att_row_r . Whw + bhw)
    if (wid < 5) {
        float p = 0.f;
        for (int dI = lane; dI < DD; dI += 32) p += att[wid * DD + dI] * Whw[dI];
        #pragma unroll
        for (int o = 16; o; o >>= 1) p += __shfl_xor_sync(0xffffffffu, p, o);
        if (lane == 0) sw[wid] = 1.0f / (1.0f + expf(-(p + bhw[0])));
    }
    __syncthreads();

    float w0 = sw[0], w1 = sw[1], w2 = sw[2], w3 = sw[3], w4 = sw[4];
    #pragma unroll
    for (int k = 0; k < 2; k++) {
        int dI = t + 256 * k;
        if (dI < DD) {
            float o = feat[(size_t)n * DD + dI];
            o += att[dI] * w0 + att[DD + dI] * w1 + att[2 * DD + dI] * w2
               + att[3 * DD + dI] * w3 + att[HD + dI] * w4;
            out[(size_t)n * DD + dI] = o;
        }
    }
}

// ---------------- launch ----------------
extern "C" void kernel_launch(void* const* d_in, const int* in_sizes, int n_in,
                              void* d_out, int out_size)
{
    const float* feat   = (const float*)d_in[0];
    const float* Wg     = (const float*)d_in[1];
    const float* attn_l = (const float*)d_in[2];
    const float* attn_r = (const float*)d_in[3];
    const float* b_gat  = (const float*)d_in[4];
    const float* Wsage  = (const float*)d_in[5];
    const float* b_sage = (const float*)d_in[6];
    const float* Whw    = (const float*)d_in[7];
    const float* bhw    = (const float*)d_in[8];
    const int*   src    = (const int*)d_in[9];
    const int*   dst    = (const int*)d_in[10];
    const int*   src1   = (const int*)d_in[11];
    const int*   dst1   = (const int*)d_in[12];
    float* out = (float*)d_out;

    const int N = in_sizes[0] / DD;
    const int E = in_sizes[9];

    float *fsrc, *el, *er, *hneigh, *sage;
    int *cntg, *cnt1, *curg, *cur1, *offsg, *offs1, *adjg, *adj1;
    cudaGetSymbolAddress((void**)&fsrc,   g_fsrc);
    cudaGetSymbolAddress((void**)&el,     g_el);
    cudaGetSymbolAddress((void**)&er,     g_er);
    cudaGetSymbolAddress((void**)&hneigh, g_neigh);
    cudaGetSymbolAddress((void**)&sage,   g_sage);
    cudaGetSymbolAddress((void**)&cntg,   g_cntg);
    cudaGetSymbolAddress((void**)&cnt1,   g_cnt1);
    cudaGetSymbolAddress((void**)&curg,   g_curg);
    cudaGetSymbolAddress((void**)&cur1,   g_cur1);
    cudaGetSymbolAddress((void**)&offsg,  g_offsg);
    cudaGetSymbolAddress((void**)&offs1,  g_offs1);
    cudaGetSymbolAddress((void**)&adjg,   g_adjg);
    cudaGetSymbolAddress((void**)&adj1,   g_adj1);

    // small memsets only (CSR counters)
    cudaMemsetAsync(cntg, 0, N * sizeof(int), 0);
    cudaMemsetAsync(cnt1, 0, N * sizeof(int), 0);
    cudaMemsetAsync(curg, 0, N * sizeof(int), 0);
    cudaMemsetAsync(cur1, 0, N * sizeof(int), 0);

    // CSR build for both graphs
    hist_kernel<<<(E + 255) / 256, 256>>>(dst, dst1, cntg, cnt1, E);
    scan2_kernel<<<2, 1024>>>(cntg, cnt1, offsg, offs1, N);
    scatter_kernel<<<(E + 255) / 256, 256>>>(src, dst, src1, dst1,
                                             offsg, offs1, curg, cur1,
                                             adjg, adj1, E);

    // GEMM1: fsrc = feat @ Wg    [N,300] @ [300,1200]
    {
        dim3 grid((HD + GBN - 1) / GBN, (N + GBM - 1) / GBM);
        gemm_tf32_kernel<<<grid, 256>>>(feat, Wg, fsrc, N, HD, DD, nullptr);
    }

    // el/er
    el_er_kernel<<<N, 128>>>(fsrc, attn_l, attn_r, el, er);

    // SAGE gcn-mean over CSR, then GEMM2
    sage_neigh_kernel<<<(N * 32 + 255) / 256, 256>>>(feat, offs1, adj1, hneigh, N);
    {
        dim3 grid((DD + GBN - 1) / GBN, (N + GBM - 1) / GBM);
        gemm_tf32_kernel<<<grid, 256>>>(hneigh, Wsage, sage, N, DD, DD, b_sage);
    }

    // fused GAT softmax + aggregation + gating + residual
    gat_final_kernel<<<N, 256>>>(fsrc, el, er, offsg, adjg,
                                 sage, feat, b_gat, Whw, bhw, out, N);
}

// round 4
// speedup vs baseline: 1.6474x; 1.6474x over previous
#include <cuda_runtime.h>
#include <math.h>

// Problem constants
#define DD 300
#define HH 4
#define HD 1200           // H*D
#define MAXN 50000
#define MAXE 200000

// ---------------- scratch (static device globals; no allocation) ----------------
__device__ __align__(16) float g_fsrc [(size_t)MAXN * HD];   // [N,H,D] = feat @ Wg
__device__ __align__(16) float g_el   [MAXN * HH];
__device__ __align__(16) float g_er   [MAXN * HH];
__device__ __align__(16) float g_neigh[(size_t)MAXN * DD];   // SAGE h_neigh
__device__ __align__(16) float g_sage [(size_t)MAXN * DD];
__device__ int g_cntg[MAXN], g_cnt1[MAXN];
__device__ int g_curg[MAXN], g_cur1[MAXN];
__device__ int g_offsg[MAXN + 1], g_offs1[MAXN + 1];
__device__ int g_adjg[MAXE], g_adj1[MAXE];

__device__ __forceinline__ unsigned f2tf32(float x) {
    unsigned r;
    asm("cvt.rna.tf32.f32 %0, %1;" : "=r"(r) : "f"(x));
    return r;
}

// ================= TF32 tensor-core GEMM, conflict-free staging =================
// C[M,Ncol] = A[M,K] @ B[K,Ncol] (+bias)
// Block tile 128x64, BK=32, 256 threads (8 warps as 4m x 2n), warp tile 32x32.
// A smem: [row][32 k words], 16B-chunk XOR swizzle (chunk ^ (row&7)).
// B smem: [k][72 words] row-major (8-word pad) -> frag gather conflict-free.
#define GBM 128
#define GBN 64
#define GBK 32

__global__ __launch_bounds__(256) void gemm_tf32_kernel(
    const float* __restrict__ A, const float* __restrict__ B, float* __restrict__ C,
    int M, int Ncol, int K, const float* __restrict__ bias)
{
    __shared__ unsigned As[128 * 32];   // 16 KB
    __shared__ unsigned Bs[32 * 72];    // 9 KB

    const int tid  = threadIdx.x;
    const int lane = tid & 31;
    const int wid  = tid >> 5;
    const int wm   = wid & 3;
    const int wn   = wid >> 2;
    const int g    = lane >> 2;
    const int tig  = lane & 3;
    const int rowBase = blockIdx.y * GBM;
    const int colBase = blockIdx.x * GBN;

    float acc[2][4][4];
    #pragma unroll
    for (int i = 0; i < 2; i++)
        #pragma unroll
        for (int j = 0; j < 4; j++)
            #pragma unroll
            for (int r = 0; r < 4; r++) acc[i][j][r] = 0.f;

    float4 ra[4];   // A prefetch: 128x32 / 256 threads = 4 float4
    float4 rb[2];   // B prefetch: 32x64 / 256 threads = 2 float4

    auto loadG = [&](int kt) {
        #pragma unroll
        for (int q = 0; q < 4; q++) {
            int idx = tid + 256 * q;
            int ar = idx >> 3, ac = (idx & 7) * 4;
            int gr = rowBase + ar, gc = kt + ac;
            float4 v = make_float4(0.f, 0.f, 0.f, 0.f);
            if (gr < M && gc < K) v = *(const float4*)(A + (size_t)gr * K + gc);
            ra[q] = v;
        }
        #pragma unroll
        for (int q = 0; q < 2; q++) {
            int idx = tid + 256 * q;
            int bk = idx >> 4, bn = (idx & 15) * 4;
            int grow = kt + bk, gc = colBase + bn;
            float4 v = make_float4(0.f, 0.f, 0.f, 0.f);
            if (grow < K && gc < Ncol) v = *(const float4*)(B + (size_t)grow * Ncol + gc);
            rb[q] = v;
        }
    };

    auto storeS = [&]() {
        #pragma unroll
        for (int q = 0; q < 4; q++) {
            int idx = tid + 256 * q;
            int ar = idx >> 3, ac4 = idx & 7;
            int word = ar * 32 + ((ac4 ^ (ar & 7)) << 2);
            uint4 w = make_uint4(f2tf32(ra[q].x), f2tf32(ra[q].y),
                                 f2tf32(ra[q].z), f2tf32(ra[q].w));
            *(uint4*)&As[word] = w;
        }
        #pragma unroll
        for (int q = 0; q < 2; q++) {
            int idx = tid + 256 * q;
            int bk = idx >> 4, bn4 = idx & 15;
            int word = bk * 72 + bn4 * 4;
            uint4 w = make_uint4(f2tf32(rb[q].x), f2tf32(rb[q].y),
                                 f2tf32(rb[q].z), f2tf32(rb[q].w));
            *(uint4*)&Bs[word] = w;
        }
    };

    const int KITERS = (K + GBK - 1) / GBK;
    loadG(0);
    storeS();
    __syncthreads();

    for (int it = 0; it < KITERS; it++) {
        if (it + 1 < KITERS) loadG((it + 1) * GBK);

        #pragma unroll
        for (int ks = 0; ks < 4; ks++) {
            unsigned af[2][4];
            #pragma unroll
            for (int mi = 0; mi < 2; mi++) {
                int mt = wm * 2 + mi;
                #pragma unroll
                for (int jj = 0; jj < 4; jj++) {
                    int hi = jj & 1, chi = jj >> 1;
                    int word = mt * 512 + hi * 256 + g * 32
                             + (((ks * 2 + chi) ^ g) << 2) + tig;
                    af[mi][jj] = As[word];
                }
            }
            unsigned bf[4][2];
            #pragma unroll
            for (int ni = 0; ni < 4; ni++) {
                int nt = wn * 4 + ni;
                #pragma unroll
                for (int jj = 0; jj < 2; jj++) {
                    int word = (ks * 8 + jj * 4 + tig) * 72 + nt * 8 + g;
                    bf[ni][jj] = Bs[word];
                }
            }
            #pragma unroll
            for (int mi = 0; mi < 2; mi++)
                #pragma unroll
                for (int ni = 0; ni < 4; ni++) {
                    asm volatile(
                        "mma.sync.aligned.m16n8k8.row.col.f32.tf32.tf32.f32 "
                        "{%0,%1,%2,%3}, {%4,%5,%6,%7}, {%8,%9}, {%0,%1,%2,%3};"
                        : "+f"(acc[mi][ni][0]), "+f"(acc[mi][ni][1]),
                          "+f"(acc[mi][ni][2]), "+f"(acc[mi][ni][3])
                        : "r"(af[mi][0]), "r"(af[mi][1]), "r"(af[mi][2]), "r"(af[mi][3]),
                          "r"(bf[ni][0]), "r"(bf[ni][1]));
                }
        }

        __syncthreads();
        if (it + 1 < KITERS) {
            storeS();
            __syncthreads();
        }
    }

    // epilogue
    #pragma unroll
    for (int mi = 0; mi < 2; mi++) {
        int grow0 = rowBase + (wm * 2 + mi) * 16 + g;
        #pragma unroll
        for (int ni = 0; ni < 4; ni++) {
            int gcol = colBase + (wn * 4 + ni) * 8 + tig * 2;
            if (gcol >= Ncol) continue;
            float b0 = 0.f, b1 = 0.f;
            if (bias) { b0 = bias[gcol]; b1 = bias[gcol + 1]; }
            if (grow0 < M) {
                float2 v = make_float2(acc[mi][ni][0] + b0, acc[mi][ni][1] + b1);
                *(float2*)(C + (size_t)grow0 * Ncol + gcol) = v;
            }
            if (grow0 + 8 < M) {
                float2 v = make_float2(acc[mi][ni][2] + b0, acc[mi][ni][3] + b1);
                *(float2*)(C + (size_t)(grow0 + 8) * Ncol + gcol) = v;
            }
        }
    }
}

// ---------------- CSR build: histogram, scan, scatter ----------------
__global__ void hist_kernel(const int* __restrict__ dst, const int* __restrict__ dst1,
                            int* __restrict__ cntg, int* __restrict__ cnt1, int E)
{
    int i = blockIdx.x * blockDim.x + threadIdx.x;
    if (i >= E) return;
    atomicAdd(&cntg[dst[i]], 1);
    atomicAdd(&cnt1[dst1[i]], 1);
}

__global__ void scan2_kernel(const int* __restrict__ cntg, const int* __restrict__ cnt1,
                             int* __restrict__ offsg, int* __restrict__ offs1, int n)
{
    const int* cnt = blockIdx.x ? cnt1 : cntg;
    int* offs = blockIdx.x ? offs1 : offsg;
    __shared__ int part[1024];
    int t = threadIdx.x;
    int chunk = (n + 1023) >> 10;
    int b = t * chunk;
    int e = min(b + chunk, n);
    int s = 0;
    for (int i = b; i < e; i++) s += cnt[i];
    part[t] = s;
    __syncthreads();
    for (int o = 1; o < 1024; o <<= 1) {
        int v = (t >= o) ? part[t - o] : 0;
        __syncthreads();
        part[t] += v;
        __syncthreads();
    }
    int ex = t ? part[t - 1] : 0;
    for (int i = b; i < e; i++) { offs[i] = ex; ex += cnt[i]; }
    if (t == 1023) offs[n] = ex;
}

__global__ void scatter_kernel(const int* __restrict__ src, const int* __restrict__ dst,
                               const int* __restrict__ src1, const int* __restrict__ dst1,
                               const int* __restrict__ offsg, const int* __restrict__ offs1,
                               int* __restrict__ curg, int* __restrict__ cur1,
                               int* __restrict__ adjg, int* __restrict__ adj1, int E)
{
    int i = blockIdx.x * blockDim.x + threadIdx.x;
    if (i >= E) return;
    int d = dst[i];
    adjg[offsg[d] + atomicAdd(&curg[d], 1)] = src[i];
    int d1 = dst1[i];
    adj1[offs1[d1] + atomicAdd(&cur1[d1], 1)] = src1[i];
}

// ---------------- el/er: per-(node,head) dot with attn_l / attn_r ----------------
__global__ void el_er_kernel(const float* __restrict__ fsrc,
                             const float* __restrict__ attn_l,
                             const float* __restrict__ attn_r,
                             float* __restrict__ el, float* __restrict__ er)
{
    int n = blockIdx.x;
    int w = threadIdx.x >> 5;
    int lane = threadIdx.x & 31;
    const float* fr = fsrc + (size_t)n * HD + w * DD;
    const float* al = attn_l + w * DD;
    const float* ar = attn_r + w * DD;
    float sl = 0.f, sr = 0.f;
    for (int d = lane; d < DD; d += 32) {
        float f = fr[d];
        sl += f * al[d];
        sr += f * ar[d];
    }
    #pragma unroll
    for (int o = 16; o; o >>= 1) {
        sl += __shfl_down_sync(0xffffffffu, sl, o);
        sr += __shfl_down_sync(0xffffffffu, sr, o);
    }
    if (lane == 0) {
        el[n * HH + w] = sl;
        er[n * HH + w] = sr;
    }
}

// ---------------- SAGE gcn-mean over CSR: warp per node ----------------
__global__ void sage_neigh_kernel(const float* __restrict__ feat,
                                  const int* __restrict__ offs1,
                                  const int* __restrict__ adj1,
                                  float* __restrict__ hneigh, int N)
{
    int n = (blockIdx.x * blockDim.x + threadIdx.x) >> 5;
    int lane = threadIdx.x & 31;
    if (n >= N) return;
    int beg = offs1[n], end = offs1[n + 1];
    float deg = (float)(end - beg);
    const float4* self = (const float4*)(feat + (size_t)n * DD);
    float4 acc[3];
    #pragma unroll
    for (int k = 0; k < 3; k++) {
        int idx = lane + 32 * k;
        if (idx < 75) acc[k] = self[idx];
    }
    for (int e = beg; e < end; e++) {
        int s = adj1[e];
        const float4* fr = (const float4*)(feat + (size_t)s * DD);
        #pragma unroll
        for (int k = 0; k < 3; k++) {
            int idx = lane + 32 * k;
            if (idx < 75) {
                float4 v = fr[idx];
                acc[k].x += v.x; acc[k].y += v.y; acc[k].z += v.z; acc[k].w += v.w;
            }
        }
    }
    float sc = 1.0f / (deg + 1.0f);
    float4* outp = (float4*)(hneigh + (size_t)n * DD);
    #pragma unroll
    for (int k = 0; k < 3; k++) {
        int idx = lane + 32 * k;
        if (idx < 75) {
            acc[k].x *= sc; acc[k].y *= sc; acc[k].z *= sc; acc[k].w *= sc;
            outp[idx] = acc[k];
        }
    }
}

__device__ __forceinline__ float lrelu(float x) { return x > 0.f ? x : 0.2f * x; }

// ---------------- fused GAT softmax + aggregation + gating + residual ----------------
// block per dst node, 256 threads
__global__ __launch_bounds__(256) void gat_final_kernel(
    const float* __restrict__ fsrc,
    const float* __restrict__ el, const float* __restrict__ er,
    const int* __restrict__ offs, const int* __restrict__ adj,
    const float* __restrict__ sage, const float* __restrict__ feat,
    const float* __restrict__ b_gat,
    const float* __restrict__ Whw, const float* __restrict__ bhw,
    float* __restrict__ out, int N)
{
    int n = blockIdx.x;
    int t = threadIdx.x;
    int lane = t & 31;
    int wid = t >> 5;

    __shared__ int   s_src[32];
    __shared__ float s_alpha[32][4];
    __shared__ __align__(16) float att[1500];   // 4x300 gat + 300 sage
    __shared__ float sw[5];

    int beg = offs[n], end = offs[n + 1];
    int deg = end - beg;

    const int h0 = t / 75;      // head of float4 index t (75 float4 per head)

    float4 acc0 = make_float4(0.f, 0.f, 0.f, 0.f);
    float4 acc1 = make_float4(0.f, 0.f, 0.f, 0.f);

    if (deg <= 32) {
        // single-pass softmax in warp 0
        if (wid == 0) {
            float4 rr = ((const float4*)er)[n];
            float v0 = -INFINITY, v1 = -INFINITY, v2 = -INFINITY, v3 = -INFINITY;
            if (lane < deg) {
                int s = adj[beg + lane];
                s_src[lane] = s;
                float4 l = ((const float4*)el)[s];
                v0 = lrelu(l.x + rr.x); v1 = lrelu(l.y + rr.y);
                v2 = lrelu(l.z + rr.z); v3 = lrelu(l.w + rr.w);
            }
            float m0 = v0, m1 = v1, m2 = v2, m3 = v3;
            #pragma unroll
            for (int o = 16; o; o >>= 1) {
                m0 = fmaxf(m0, __shfl_xor_sync(0xffffffffu, m0, o));
                m1 = fmaxf(m1, __shfl_xor_sync(0xffffffffu, m1, o));
                m2 = fmaxf(m2, __shfl_xor_sync(0xffffffffu, m2, o));
                m3 = fmaxf(m3, __shfl_xor_sync(0xffffffffu, m3, o));
            }
            float x0 = (lane < deg) ? expf(v0 - m0) : 0.f;
            float x1 = (lane < deg) ? expf(v1 - m1) : 0.f;
            float x2 = (lane < deg) ? expf(v2 - m2) : 0.f;
            float x3 = (lane < deg) ? expf(v3 - m3) : 0.f;
            float z0 = x0, z1 = x1, z2 = x2, z3 = x3;
            #pragma unroll
            for (int o = 16; o; o >>= 1) {
                z0 += __shfl_xor_sync(0xffffffffu, z0, o);
                z1 += __shfl_xor_sync(0xffffffffu, z1, o);
                z2 += __shfl_xor_sync(0xffffffffu, z2, o);
                z3 += __shfl_xor_sync(0xffffffffu, z3, o);
            }
            if (lane < deg) {
                s_alpha[lane][0] = x0 / z0;
                s_alpha[lane][1] = x1 / z1;
                s_alpha[lane][2] = x2 / z2;
                s_alpha[lane][3] = x3 / z3;
            }
        }
        __syncthreads();
        for (int j = 0; j < deg; j++) {
            int s = s_src[j];
            const float4* fr = (const float4*)(fsrc + (size_t)s * HD);
            float a0 = s_alpha[j][h0];
            float4 v = fr[t];
            acc0.x += a0 * v.x; acc0.y += a0 * v.y;
            acc0.z += a0 * v.z; acc0.w += a0 * v.w;
            if (t < 44) {
                float a1 = s_alpha[j][3];
                float4 v1 = fr[t + 256];
                acc1.x += a1 * v1.x; acc1.y += a1 * v1.y;
                acc1.z += a1 * v1.z; acc1.w += a1 * v1.w;
            }
        }
        __syncthreads();
    } else {
        // general path: 2-pass softmax stats in warp 0, then chunked aggregation
        float m0 = -INFINITY, m1 = -INFINITY, m2 = -INFINITY, m3 = -INFINITY;
        float z0 = 0.f, z1 = 0.f, z2 = 0.f, z3 = 0.f;
        float4 rr = make_float4(0.f, 0.f, 0.f, 0.f);
        if (wid == 0) {
            rr = ((const float4*)er)[n];
            for (int i = lane; i < deg; i += 32) {
                int s = adj[beg + i];
                float4 l = ((const float4*)el)[s];
                m0 = fmaxf(m0, lrelu(l.x + rr.x)); m1 = fmaxf(m1, lrelu(l.y + rr.y));
                m2 = fmaxf(m2, lrelu(l.z + rr.z)); m3 = fmaxf(m3, lrelu(l.w + rr.w));
            }
            #pragma unroll
            for (int o = 16; o; o >>= 1) {
                m0 = fmaxf(m0, __shfl_xor_sync(0xffffffffu, m0, o));
                m1 = fmaxf(m1, __shfl_xor_sync(0xffffffffu, m1, o));
                m2 = fmaxf(m2, __shfl_xor_sync(0xffffffffu, m2, o));
                m3 = fmaxf(m3, __shfl_xor_sync(0xffffffffu, m3, o));
            }
            for (int i = lane; i < deg; i += 32) {
                int s = adj[beg + i];
                float4 l = ((const float4*)el)[s];
                z0 += expf(lrelu(l.x + rr.x) - m0); z1 += expf(lrelu(l.y + rr.y) - m1);
                z2 += expf(lrelu(l.z + rr.z) - m2); z3 += expf(lrelu(l.w + rr.w) - m3);
            }
            #pragma unroll
            for (int o = 16; o; o >>= 1) {
                z0 += __shfl_xor_sync(0xffffffffu, z0, o);
                z1 += __shfl_xor_sync(0xffffffffu, z1, o);
                z2 += __shfl_xor_sync(0xffffffffu, z2, o);
                z3 += __shfl_xor_sync(0xffffffffu, z3, o);
            }
        }
        for (int c = 0; c < deg; c += 32) {
            int cn = min(32, deg - c);
            __syncthreads();
            if (wid == 0 && lane < cn) {
                int s = adj[beg + c + lane];
                s_src[lane] = s;
                float4 l = ((const float4*)el)[s];
                s_alpha[lane][0] = expf(lrelu(l.x + rr.x) - m0) / z0;
                s_alpha[lane][1] = expf(lrelu(l.y + rr.y) - m1) / z1;
                s_alpha[lane][2] = expf(lrelu(l.z + rr.z) - m2) / z2;
                s_alpha[lane][3] = expf(lrelu(l.w + rr.w) - m3) / z3;
            }
            __syncthreads();
            for (int j = 0; j < cn; j++) {
                int s = s_src[j];
                const float4* fr = (const float4*)(fsrc + (size_t)s * HD);
                float a0 = s_alpha[j][h0];
                float4 v = fr[t];
                acc0.x += a0 * v.x; acc0.y += a0 * v.y;
                acc0.z += a0 * v.z; acc0.w += a0 * v.w;
                if (t < 44) {
                    float a1 = s_alpha[j][3];
                    float4 v1 = fr[t + 256];
                    acc1.x += a1 * v1.x; acc1.y += a1 * v1.y;
                    acc1.z += a1 * v1.z; acc1.w += a1 * v1.w;
                }
            }
        }
        __syncthreads();
    }

    // stage att rows: gat heads + b_gat, then sage row
    {
        float4* att4 = (float4*)att;
        const float4* bg4 = (const float4*)b_gat;
        float4 b = bg4[t];
        att4[t] = make_float4(acc0.x + b.x, acc0.y + b.y, acc0.z + b.z, acc0.w + b.w);
        if (t < 44) {
            float4 b1 = bg4[t + 256];
            att4[t + 256] = make_float4(acc1.x + b1.x, acc1.y + b1.y,
                                        acc1.z + b1.z, acc1.w + b1.w);
        }
        const float4* sg4 = (const float4*)(sage + (size_t)n * DD);
        if (t < 75) att4[300 + t] = sg4[t];
    }
    __syncthreads();

    // gating: warp r computes sigmoid(att_row_r . Whw + bhw)
    if (wid < 5) {
        float p = 0.f;
        for (int dI = lane; dI < DD; dI += 32) p += att[wid * DD + dI] * Whw[dI];
        #pragma unroll
        for (int o = 16; o; o >>= 1) p += __shfl_xor_sync(0xffffffffu, p, o);
        if (lane == 0) sw[wid] = 1.0f / (1.0f + expf(-(p + bhw[0])));
    }
    __syncthreads();

    float w0 = sw[0], w1 = sw[1], w2 = sw[2], w3 = sw[3], w4 = sw[4];
    #pragma unroll
    for (int k = 0; k < 2; k++) {
        int dI = t + 256 * k;
        if (dI < DD) {
            float o = feat[(size_t)n * DD + dI];
            o += att[dI] * w0 + att[DD + dI] * w1 + att[2 * DD + dI] * w2
               + att[3 * DD + dI] * w3 + att[HD + dI] * w4;
            out[(size_t)n * DD + dI] = o;
        }
    }
}

// ---------------- launch ----------------
extern "C" void kernel_launch(void* const* d_in, const int* in_sizes, int n_in,
                              void* d_out, int out_size)
{
    const float* feat   = (const float*)d_in[0];
    const float* Wg     = (const float*)d_in[1];
    const float* attn_l = (const float*)d_in[2];
    const float* attn_r = (const float*)d_in[3];
    const float* b_gat  = (const float*)d_in[4];
    const float* Wsage  = (const float*)d_in[5];
    const float* b_sage = (const float*)d_in[6];
    const float* Whw    = (const float*)d_in[7];
    const float* bhw    = (const float*)d_in[8];
    const int*   src    = (const int*)d_in[9];
    const int*   dst    = (const int*)d_in[10];
    const int*   src1   = (const int*)d_in[11];
    const int*   dst1   = (const int*)d_in[12];
    float* out = (float*)d_out;

    const int N = in_sizes[0] / DD;
    const int E = in_sizes[9];

    float *fsrc, *el, *er, *hneigh, *sage;
    int *cntg, *cnt1, *curg, *cur1, *offsg, *offs1, *adjg, *adj1;
    cudaGetSymbolAddress((void**)&fsrc,   g_fsrc);
    cudaGetSymbolAddress((void**)&el,     g_el);
    cudaGetSymbolAddress((void**)&er,     g_er);
    cudaGetSymbolAddress((void**)&hneigh, g_neigh);
    cudaGetSymbolAddress((void**)&sage,   g_sage);
    cudaGetSymbolAddress((void**)&cntg,   g_cntg);
    cudaGetSymbolAddress((void**)&cnt1,   g_cnt1);
    cudaGetSymbolAddress((void**)&curg,   g_curg);
    cudaGetSymbolAddress((void**)&cur1,   g_cur1);
    cudaGetSymbolAddress((void**)&offsg,  g_offsg);
    cudaGetSymbolAddress((void**)&offs1,  g_offs1);
    cudaGetSymbolAddress((void**)&adjg,   g_adjg);
    cudaGetSymbolAddress((void**)&adj1,   g_adj1);

    // small memsets only (CSR counters)
    cudaMemsetAsync(cntg, 0, N * sizeof(int), 0);
    cudaMemsetAsync(cnt1, 0, N * sizeof(int), 0);
    cudaMemsetAsync(curg, 0, N * sizeof(int), 0);
    cudaMemsetAsync(cur1, 0, N * sizeof(int), 0);

    // CSR build for both graphs
    hist_kernel<<<(E + 255) / 256, 256>>>(dst, dst1, cntg, cnt1, E);
    scan2_kernel<<<2, 1024>>>(cntg, cnt1, offsg, offs1, N);
    scatter_kernel<<<(E + 255) / 256, 256>>>(src, dst, src1, dst1,
                                             offsg, offs1, curg, cur1,
                                             adjg, adj1, E);

    // GEMM1: fsrc = feat @ Wg    [N,300] @ [300,1200]
    {
        dim3 grid((HD + GBN - 1) / GBN, (N + GBM - 1) / GBM);
        gemm_tf32_kernel<<<grid, 256>>>(feat, Wg, fsrc, N, HD, DD, nullptr);
    }

    // el/er
    el_er_kernel<<<N, 128>>>(fsrc, attn_l, attn_r, el, er);

    // SAGE gcn-mean over CSR, then GEMM2
    sage_neigh_kernel<<<(N * 32 + 255) / 256, 256>>>(feat, offs1, adj1, hneigh, N);
    {
        dim3 grid((DD + GBN - 1) / GBN, (N + GBM - 1) / GBM);
        gemm_tf32_kernel<<<grid, 256>>>(hneigh, Wsage, sage, N, DD, DD, b_sage);
    }

    // fused GAT softmax + aggregation + gating + residual
    gat_final_kernel<<<N, 256>>>(fsrc, el, er, offsg, adjg,
                                 sage, feat, b_gat, Whw, bhw, out, N);
}

// round 5
// speedup vs baseline: 1.6883x; 1.0249x over previous
#include <cuda_runtime.h>
#include <math.h>

// Problem constants
#define DD 300
#define HH 4
#define HD 1200           // H*D
#define MAXN 50000
#define MAXE 200000

// ---------------- scratch (static device globals; no allocation) ----------------
__device__ __align__(16) float g_fsrc [(size_t)MAXN * HD];   // [N,H,D] = feat @ Wg
__device__ __align__(16) float g_el   [MAXN * HH];
__device__ __align__(16) float g_er   [MAXN * HH];
__device__ __align__(16) float g_neigh[(size_t)MAXN * DD];   // SAGE h_neigh
__device__ __align__(16) float g_sage [(size_t)MAXN * DD];
__device__ int g_cntg[MAXN], g_cnt1[MAXN];
__device__ int g_curg[MAXN], g_cur1[MAXN];
__device__ int g_offsg[MAXN + 1], g_offs1[MAXN + 1];
__device__ int g_adjg[MAXE], g_adj1[MAXE];

// ---------------- cp.async helpers ----------------
__device__ __forceinline__ void cp16(unsigned dst, const void* src, bool full) {
    asm volatile(
        "{\n\t.reg .pred p;\n\tsetp.ne.u32 p, %2, 0;\n\t"
        "@p cp.async.ca.shared.global [%0], [%1], 16;\n\t"
        "@!p cp.async.ca.shared.global [%0], [%1], 16, 0;\n\t}\n"
        :: "r"(dst), "l"(src), "r"((unsigned)full) : "memory");
}
__device__ __forceinline__ void cp_commit() {
    asm volatile("cp.async.commit_group;" ::: "memory");
}
template<int N>
__device__ __forceinline__ void cp_wait() {
    asm volatile("cp.async.wait_group %0;" :: "n"(N) : "memory");
}

// ================= TF32 tensor-core GEMM, cp.async double-buffered =================
// C[M,Ncol] = A[M,K] @ B[K,Ncol] (+bias)
// Block tile 128x64, BK=32, 256 threads (8 warps as 4m x 2n), warp tile 32x32.
// A smem: [row][32 k words], 16B-chunk XOR swizzle (chunk ^ (row&7)).
// B smem: [k][72 words] row-major (8-word pad).
// fp32 bits fed directly as tf32 operands (truncation; no cvt).
#define GBM 128
#define GBN 64
#define GBK 32
#define A_WORDS (128 * 32)      // per buffer
#define B_WORDS (32 * 72)
#define GEMM_SMEM ((2 * A_WORDS + 2 * B_WORDS) * 4)

__global__ __launch_bounds__(256) void gemm_tf32_kernel(
    const float* __restrict__ A, const float* __restrict__ B, float* __restrict__ C,
    int M, int Ncol, int K, const float* __restrict__ bias)
{
    extern __shared__ __align__(16) unsigned smem[];
    unsigned* As = smem;                      // [2][A_WORDS]
    unsigned* Bs = smem + 2 * A_WORDS;        // [2][B_WORDS]
    const unsigned smem_base = (unsigned)__cvta_generic_to_shared(smem);

    const int tid  = threadIdx.x;
    const int lane = tid & 31;
    const int wid  = tid >> 5;
    const int wm   = wid & 3;
    const int wn   = wid >> 2;
    const int g    = lane >> 2;
    const int tig  = lane & 3;
    const int rowBase = blockIdx.y * GBM;
    const int colBase = blockIdx.x * GBN;

    float acc[2][4][4];
    #pragma unroll
    for (int i = 0; i < 2; i++)
        #pragma unroll
        for (int j = 0; j < 4; j++)
            #pragma unroll
            for (int r = 0; r < 4; r++) acc[i][j][r] = 0.f;

    // precomputed per-thread staging coordinates
    auto issue = [&](int kt, int buf) {
        unsigned abase = smem_base + buf * (A_WORDS * 4);
        unsigned bbase = smem_base + (2 * A_WORDS + buf * B_WORDS) * 4;
        #pragma unroll
        for (int q = 0; q < 4; q++) {
            int idx = tid + 256 * q;
            int ar = idx >> 3, ac4 = idx & 7;
            int gr = rowBase + ar, gc = kt + ac4 * 4;
            bool ok = (gr < M) && (gc + 4 <= K);
            const float* src = ok ? (A + (size_t)gr * K + gc) : A;
            unsigned word = ar * 32 + ((ac4 ^ (ar & 7)) << 2);
            cp16(abase + word * 4, src, ok);
        }
        #pragma unroll
        for (int q = 0; q < 2; q++) {
            int idx = tid + 256 * q;
            int bk = idx >> 4, bn4 = idx & 15;
            int grow = kt + bk, gc = colBase + bn4 * 4;
            bool ok = (grow < K) && (gc + 4 <= Ncol);
            const float* src = ok ? (B + (size_t)grow * Ncol + gc) : B;
            unsigned word = bk * 72 + bn4 * 4;
            cp16(bbase + word * 4, src, ok);
        }
        cp_commit();
    };

    const int KITERS = (K + GBK - 1) / GBK;
    issue(0, 0);

    for (int it = 0; it < KITERS; it++) {
        int cur = it & 1;
        if (it + 1 < KITERS) {
            issue((it + 1) * GBK, cur ^ 1);
            cp_wait<1>();
        } else {
            cp_wait<0>();
        }
        __syncthreads();

        const unsigned* Ab = As + cur * A_WORDS;
        const unsigned* Bb = Bs + cur * B_WORDS;

        #pragma unroll
        for (int ks = 0; ks < 4; ks++) {
            unsigned af[2][4];
            #pragma unroll
            for (int mi = 0; mi < 2; mi++) {
                int mt = wm * 2 + mi;
                #pragma unroll
                for (int jj = 0; jj < 4; jj++) {
                    int hi = jj & 1, chi = jj >> 1;
                    int word = mt * 512 + hi * 256 + g * 32
                             + (((ks * 2 + chi) ^ g) << 2) + tig;
                    af[mi][jj] = Ab[word];
                }
            }
            unsigned bf[4][2];
            #pragma unroll
            for (int ni = 0; ni < 4; ni++) {
                int nt = wn * 4 + ni;
                #pragma unroll
                for (int jj = 0; jj < 2; jj++) {
                    int word = (ks * 8 + jj * 4 + tig) * 72 + nt * 8 + g;
                    bf[ni][jj] = Bb[word];
                }
            }
            #pragma unroll
            for (int mi = 0; mi < 2; mi++)
                #pragma unroll
                for (int ni = 0; ni < 4; ni++) {
                    asm volatile(
                        "mma.sync.aligned.m16n8k8.row.col.f32.tf32.tf32.f32 "
                        "{%0,%1,%2,%3}, {%4,%5,%6,%7}, {%8,%9}, {%0,%1,%2,%3};"
                        : "+f"(acc[mi][ni][0]), "+f"(acc[mi][ni][1]),
                          "+f"(acc[mi][ni][2]), "+f"(acc[mi][ni][3])
                        : "r"(af[mi][0]), "r"(af[mi][1]), "r"(af[mi][2]), "r"(af[mi][3]),
                          "r"(bf[ni][0]), "r"(bf[ni][1]));
                }
        }
        __syncthreads();
    }

    // epilogue
    #pragma unroll
    for (int mi = 0; mi < 2; mi++) {
        int grow0 = rowBase + (wm * 2 + mi) * 16 + g;
        #pragma unroll
        for (int ni = 0; ni < 4; ni++) {
            int gcol = colBase + (wn * 4 + ni) * 8 + tig * 2;
            if (gcol >= Ncol) continue;
            float b0 = 0.f, b1 = 0.f;
            if (bias) { b0 = bias[gcol]; b1 = bias[gcol + 1]; }
            if (grow0 < M) {
                float2 v = make_float2(acc[mi][ni][0] + b0, acc[mi][ni][1] + b1);
                *(float2*)(C + (size_t)grow0 * Ncol + gcol) = v;
            }
            if (grow0 + 8 < M) {
                float2 v = make_float2(acc[mi][ni][2] + b0, acc[mi][ni][3] + b1);
                *(float2*)(C + (size_t)(grow0 + 8) * Ncol + gcol) = v;
            }
        }
    }
}

// ---------------- CSR build: histogram, scan, scatter ----------------
__global__ void hist_kernel(const int* __restrict__ dst, const int* __restrict__ dst1,
                            int* __restrict__ cntg, int* __restrict__ cnt1, int E)
{
    int i = blockIdx.x * blockDim.x + threadIdx.x;
    if (i >= E) return;
    atomicAdd(&cntg[dst[i]], 1);
    atomicAdd(&cnt1[dst1[i]], 1);
}

__global__ void scan2_kernel(const int* __restrict__ cntg, const int* __restrict__ cnt1,
                             int* __restrict__ offsg, int* __restrict__ offs1, int n)
{
    const int* cnt = blockIdx.x ? cnt1 : cntg;
    int* offs = blockIdx.x ? offs1 : offsg;
    __shared__ int part[1024];
    int t = threadIdx.x;
    int chunk = (n + 1023) >> 10;
    int b = t * chunk;
    int e = min(b + chunk, n);
    int s = 0;
    for (int i = b; i < e; i++) s += cnt[i];
    part[t] = s;
    __syncthreads();
    for (int o = 1; o < 1024; o <<= 1) {
        int v = (t >= o) ? part[t - o] : 0;
        __syncthreads();
        part[t] += v;
        __syncthreads();
    }
    int ex = t ? part[t - 1] : 0;
    for (int i = b; i < e; i++) { offs[i] = ex; ex += cnt[i]; }
    if (t == 1023) offs[n] = ex;
}

__global__ void scatter_kernel(const int* __restrict__ src, const int* __restrict__ dst,
                               const int* __restrict__ src1, const int* __restrict__ dst1,
                               const int* __restrict__ offsg, const int* __restrict__ offs1,
                               int* __restrict__ curg, int* __restrict__ cur1,
                               int* __restrict__ adjg, int* __restrict__ adj1, int E)
{
    int i = blockIdx.x * blockDim.x + threadIdx.x;
    if (i >= E) return;
    int d = dst[i];
    adjg[offsg[d] + atomicAdd(&curg[d], 1)] = src[i];
    int d1 = dst1[i];
    adj1[offs1[d1] + atomicAdd(&cur1[d1], 1)] = src1[i];
}

// ---------------- el/er: per-(node,head) dot with attn_l / attn_r ----------------
__global__ void el_er_kernel(const float* __restrict__ fsrc,
                             const float* __restrict__ attn_l,
                             const float* __restrict__ attn_r,
                             float* __restrict__ el, float* __restrict__ er)
{
    int n = blockIdx.x;
    int w = threadIdx.x >> 5;
    int lane = threadIdx.x & 31;
    const float* fr = fsrc + (size_t)n * HD + w * DD;
    const float* al = attn_l + w * DD;
    const float* ar = attn_r + w * DD;
    float sl = 0.f, sr = 0.f;
    for (int d = lane; d < DD; d += 32) {
        float f = fr[d];
        sl += f * al[d];
        sr += f * ar[d];
    }
    #pragma unroll
    for (int o = 16; o; o >>= 1) {
        sl += __shfl_down_sync(0xffffffffu, sl, o);
        sr += __shfl_down_sync(0xffffffffu, sr, o);
    }
    if (lane == 0) {
        el[n * HH + w] = sl;
        er[n * HH + w] = sr;
    }
}

// ---------------- SAGE gcn-mean over CSR: warp per node ----------------
__global__ void sage_neigh_kernel(const float* __restrict__ feat,
                                  const int* __restrict__ offs1,
                                  const int* __restrict__ adj1,
                                  float* __restrict__ hneigh, int N)
{
    int n = (blockIdx.x * blockDim.x + threadIdx.x) >> 5;
    int lane = threadIdx.x & 31;
    if (n >= N) return;
    int beg = offs1[n], end = offs1[n + 1];
    float deg = (float)(end - beg);
    const float4* self = (const float4*)(feat + (size_t)n * DD);
    float4 acc[3];
    #pragma unroll
    for (int k = 0; k < 3; k++) {
        int idx = lane + 32 * k;
        if (idx < 75) acc[k] = self[idx];
    }
    for (int e = beg; e < end; e++) {
        int s = adj1[e];
        const float4* fr = (const float4*)(feat + (size_t)s * DD);
        #pragma unroll
        for (int k = 0; k < 3; k++) {
            int idx = lane + 32 * k;
            if (idx < 75) {
                float4 v = fr[idx];
                acc[k].x += v.x; acc[k].y += v.y; acc[k].z += v.z; acc[k].w += v.w;
            }
        }
    }
    float sc = 1.0f / (deg + 1.0f);
    float4* outp = (float4*)(hneigh + (size_t)n * DD);
    #pragma unroll
    for (int k = 0; k < 3; k++) {
        int idx = lane + 32 * k;
        if (idx < 75) {
            acc[k].x *= sc; acc[k].y *= sc; acc[k].z *= sc; acc[k].w *= sc;
            outp[idx] = acc[k];
        }
    }
}

__device__ __forceinline__ float lrelu(float x) { return x > 0.f ? x : 0.2f * x; }

// ---------------- fused GAT softmax + aggregation + gating + residual ----------------
// block per dst node, 256 threads
__global__ __launch_bounds__(256) void gat_final_kernel(
    const float* __restrict__ fsrc,
    const float* __restrict__ el, const float* __restrict__ er,
    const int* __restrict__ offs, const int* __restrict__ adj,
    const float* __restrict__ sage, const float* __restrict__ feat,
    const float* __restrict__ b_gat,
    const float* __restrict__ Whw, const float* __restrict__ bhw,
    float* __restrict__ out, int N)
{
    int n = blockIdx.x;
    int t = threadIdx.x;
    int lane = t & 31;
    int wid = t >> 5;

    __shared__ int   s_src[32];
    __shared__ float s_alpha[32][4];
    __shared__ __align__(16) float att[1500];   // 4x300 gat + 300 sage
    __shared__ float sw[5];

    int beg = offs[n], end = offs[n + 1];
    int deg = end - beg;

    const int h0 = t / 75;      // head of float4 index t (75 float4 per head)

    float4 acc0 = make_float4(0.f, 0.f, 0.f, 0.f);
    float4 acc1 = make_float4(0.f, 0.f, 0.f, 0.f);

    if (deg <= 32) {
        // single-pass softmax in warp 0
        if (wid == 0) {
            float4 rr = ((const float4*)er)[n];
            float v0 = -INFINITY, v1 = -INFINITY, v2 = -INFINITY, v3 = -INFINITY;
            if (lane < deg) {
                int s = adj[beg + lane];
                s_src[lane] = s;
                float4 l = ((const float4*)el)[s];
                v0 = lrelu(l.x + rr.x); v1 = lrelu(l.y + rr.y);
                v2 = lrelu(l.z + rr.z); v3 = lrelu(l.w + rr.w);
            }
            float m0 = v0, m1 = v1, m2 = v2, m3 = v3;
            #pragma unroll
            for (int o = 16; o; o >>= 1) {
                m0 = fmaxf(m0, __shfl_xor_sync(0xffffffffu, m0, o));
                m1 = fmaxf(m1, __shfl_xor_sync(0xffffffffu, m1, o));
                m2 = fmaxf(m2, __shfl_xor_sync(0xffffffffu, m2, o));
                m3 = fmaxf(m3, __shfl_xor_sync(0xffffffffu, m3, o));
            }
            float x0 = (lane < deg) ? expf(v0 - m0) : 0.f;
            float x1 = (lane < deg) ? expf(v1 - m1) : 0.f;
            float x2 = (lane < deg) ? expf(v2 - m2) : 0.f;
            float x3 = (lane < deg) ? expf(v3 - m3) : 0.f;
            float z0 = x0, z1 = x1, z2 = x2, z3 = x3;
            #pragma unroll
            for (int o = 16; o; o >>= 1) {
                z0 += __shfl_xor_sync(0xffffffffu, z0, o);
                z1 += __shfl_xor_sync(0xffffffffu, z1, o);
                z2 += __shfl_xor_sync(0xffffffffu, z2, o);
                z3 += __shfl_xor_sync(0xffffffffu, z3, o);
            }
            if (lane < deg) {
                s_alpha[lane][0] = x0 / z0;
                s_alpha[lane][1] = x1 / z1;
                s_alpha[lane][2] = x2 / z2;
                s_alpha[lane][3] = x3 / z3;
            }
        }
        __syncthreads();
        for (int j = 0; j < deg; j++) {
            int s = s_src[j];
            const float4* fr = (const float4*)(fsrc + (size_t)s * HD);
            float a0 = s_alpha[j][h0];
            float4 v = fr[t];
            acc0.x += a0 * v.x; acc0.y += a0 * v.y;
            acc0.z += a0 * v.z; acc0.w += a0 * v.w;
            if (t < 44) {
                float a1 = s_alpha[j][3];
                float4 v1 = fr[t + 256];
                acc1.x += a1 * v1.x; acc1.y += a1 * v1.y;
                acc1.z += a1 * v1.z; acc1.w += a1 * v1.w;
            }
        }
        __syncthreads();
    } else {
        // general path: 2-pass softmax stats in warp 0, then chunked aggregation
        float m0 = -INFINITY, m1 = -INFINITY, m2 = -INFINITY, m3 = -INFINITY;
        float z0 = 0.f, z1 = 0.f, z2 = 0.f, z3 = 0.f;
        float4 rr = make_float4(0.f, 0.f, 0.f, 0.f);
        if (wid == 0) {
            rr = ((const float4*)er)[n];
            for (int i = lane; i < deg; i += 32) {
                int s = adj[beg + i];
                float4 l = ((const float4*)el)[s];
                m0 = fmaxf(m0, lrelu(l.x + rr.x)); m1 = fmaxf(m1, lrelu(l.y + rr.y));
                m2 = fmaxf(m2, lrelu(l.z + rr.z)); m3 = fmaxf(m3, lrelu(l.w + rr.w));
            }
            #pragma unroll
            for (int o = 16; o; o >>= 1) {
                m0 = fmaxf(m0, __shfl_xor_sync(0xffffffffu, m0, o));
                m1 = fmaxf(m1, __shfl_xor_sync(0xffffffffu, m1, o));
                m2 = fmaxf(m2, __shfl_xor_sync(0xffffffffu, m2, o));
                m3 = fmaxf(m3, __shfl_xor_sync(0xffffffffu, m3, o));
            }
            for (int i = lane; i < deg; i += 32) {
                int s = adj[beg + i];
                float4 l = ((const float4*)el)[s];
                z0 += expf(lrelu(l.x + rr.x) - m0); z1 += expf(lrelu(l.y + rr.y) - m1);
                z2 += expf(lrelu(l.z + rr.z) - m2); z3 += expf(lrelu(l.w + rr.w) - m3);
            }
            #pragma unroll
            for (int o = 16; o; o >>= 1) {
                z0 += __shfl_xor_sync(0xffffffffu, z0, o);
                z1 += __shfl_xor_sync(0xffffffffu, z1, o);
                z2 += __shfl_xor_sync(0xffffffffu, z2, o);
                z3 += __shfl_xor_sync(0xffffffffu, z3, o);
            }
        }
        for (int c = 0; c < deg; c += 32) {
            int cn = min(32, deg - c);
            __syncthreads();
            if (wid == 0 && lane < cn) {
                int s = adj[beg + c + lane];
                s_src[lane] = s;
                float4 l = ((const float4*)el)[s];
                s_alpha[lane][0] = expf(lrelu(l.x + rr.x) - m0) / z0;
                s_alpha[lane][1] = expf(lrelu(l.y + rr.y) - m1) / z1;
                s_alpha[lane][2] = expf(lrelu(l.z + rr.z) - m2) / z2;
                s_alpha[lane][3] = expf(lrelu(l.w + rr.w) - m3) / z3;
            }
            __syncthreads();
            for (int j = 0; j < cn; j++) {
                int s = s_src[j];
                const float4* fr = (const float4*)(fsrc + (size_t)s * HD);
                float a0 = s_alpha[j][h0];
                float4 v = fr[t];
                acc0.x += a0 * v.x; acc0.y += a0 * v.y;
                acc0.z += a0 * v.z; acc0.w += a0 * v.w;
                if (t < 44) {
                    float a1 = s_alpha[j][3];
                    float4 v1 = fr[t + 256];
                    acc1.x += a1 * v1.x; acc1.y += a1 * v1.y;
                    acc1.z += a1 * v1.z; acc1.w += a1 * v1.w;
                }
            }
        }
        __syncthreads();
    }

    // stage att rows: gat heads + b_gat, then sage row
    {
        float4* att4 = (float4*)att;
        const float4* bg4 = (const float4*)b_gat;
        float4 b = bg4[t];
        att4[t] = make_float4(acc0.x + b.x, acc0.y + b.y, acc0.z + b.z, acc0.w + b.w);
        if (t < 44) {
            float4 b1 = bg4[t + 256];
            att4[t + 256] = make_float4(acc1.x + b1.x, acc1.y + b1.y,
                                        acc1.z + b1.z, acc1.w + b1.w);
        }
        const float4* sg4 = (const float4*)(sage + (size_t)n * DD);
        if (t < 75) att4[300 + t] = sg4[t];
    }
    __syncthreads();

    // gating: warp r computes sigmoid(att_row_r . Whw + bhw)
    if (wid < 5) {
        float p = 0.f;
        for (int dI = lane; dI < DD; dI += 32) p += att[wid * DD + dI] * Whw[dI];
        #pragma unroll
        for (int o = 16; o; o >>= 1) p += __shfl_xor_sync(0xffffffffu, p, o);
        if (lane == 0) sw[wid] = 1.0f / (1.0f + expf(-(p + bhw[0])));
    }
    __syncthreads();

    float w0 = sw[0], w1 = sw[1], w2 = sw[2], w3 = sw[3], w4 = sw[4];
    #pragma unroll
    for (int k = 0; k < 2; k++) {
        int dI = t + 256 * k;
        if (dI < DD) {
            float o = feat[(size_t)n * DD + dI];
            o += att[dI] * w0 + att[DD + dI] * w1 + att[2 * DD + dI] * w2
               + att[3 * DD + dI] * w3 + att[HD + dI] * w4;
            out[(size_t)n * DD + dI] = o;
        }
    }
}

// ---------------- launch ----------------
extern "C" void kernel_launch(void* const* d_in, const int* in_sizes, int n_in,
                              void* d_out, int out_size)
{
    const float* feat   = (const float*)d_in[0];
    const float* Wg     = (const float*)d_in[1];
    const float* attn_l = (const float*)d_in[2];
    const float* attn_r = (const float*)d_in[3];
    const float* b_gat  = (const float*)d_in[4];
    const float* Wsage  = (const float*)d_in[5];
    const float* b_sage = (const float*)d_in[6];
    const float* Whw    = (const float*)d_in[7];
    const float* bhw    = (const float*)d_in[8];
    const int*   src    = (const int*)d_in[9];
    const int*   dst    = (const int*)d_in[10];
    const int*   src1   = (const int*)d_in[11];
    const int*   dst1   = (const int*)d_in[12];
    float* out = (float*)d_out;

    const int N = in_sizes[0] / DD;
    const int E = in_sizes[9];

    float *fsrc, *el, *er, *hneigh, *sage;
    int *cntg, *cnt1, *curg, *cur1, *offsg, *offs1, *adjg, *adj1;
    cudaGetSymbolAddress((void**)&fsrc,   g_fsrc);
    cudaGetSymbolAddress((void**)&el,     g_el);
    cudaGetSymbolAddress((void**)&er,     g_er);
    cudaGetSymbolAddress((void**)&hneigh, g_neigh);
    cudaGetSymbolAddress((void**)&sage,   g_sage);
    cudaGetSymbolAddress((void**)&cntg,   g_cntg);
    cudaGetSymbolAddress((void**)&cnt1,   g_cnt1);
    cudaGetSymbolAddress((void**)&curg,   g_curg);
    cudaGetSymbolAddress((void**)&cur1,   g_cur1);
    cudaGetSymbolAddress((void**)&offsg,  g_offsg);
    cudaGetSymbolAddress((void**)&offs1,  g_offs1);
    cudaGetSymbolAddress((void**)&adjg,   g_adjg);
    cudaGetSymbolAddress((void**)&adj1,   g_adj1);

    static int smem_set = 0;
    if (!smem_set) {
        cudaFuncSetAttribute(gemm_tf32_kernel,
                             cudaFuncAttributeMaxDynamicSharedMemorySize, GEMM_SMEM);
        smem_set = 1;
    }

    // small memsets only (CSR counters)
    cudaMemsetAsync(cntg, 0, N * sizeof(int), 0);
    cudaMemsetAsync(cnt1, 0, N * sizeof(int), 0);
    cudaMemsetAsync(curg, 0, N * sizeof(int), 0);
    cudaMemsetAsync(cur1, 0, N * sizeof(int), 0);

    // CSR build for both graphs
    hist_kernel<<<(E + 255) / 256, 256>>>(dst, dst1, cntg, cnt1, E);
    scan2_kernel<<<2, 1024>>>(cntg, cnt1, offsg, offs1, N);
    scatter_kernel<<<(E + 255) / 256, 256>>>(src, dst, src1, dst1,
                                             offsg, offs1, curg, cur1,
                                             adjg, adj1, E);

    // GEMM1: fsrc = feat @ Wg    [N,300] @ [300,1200]
    {
        dim3 grid((HD + GBN - 1) / GBN, (N + GBM - 1) / GBM);
        gemm_tf32_kernel<<<grid, 256, GEMM_SMEM>>>(feat, Wg, fsrc, N, HD, DD, nullptr);
    }

    // el/er
    el_er_kernel<<<N, 128>>>(fsrc, attn_l, attn_r, el, er);

    // SAGE gcn-mean over CSR, then GEMM2
    sage_neigh_kernel<<<(N * 32 + 255) / 256, 256>>>(feat, offs1, adj1, hneigh, N);
    {
        dim3 grid((DD + GBN - 1) / GBN, (N + GBM - 1) / GBM);
        gemm_tf32_kernel<<<grid, 256, GEMM_SMEM>>>(hneigh, Wsage, sage, N, DD, DD, b_sage);
    }

    // fused GAT softmax + aggregation + gating + residual
    gat_final_kernel<<<N, 256>>>(fsrc, el, er, offsg, adjg,
                                 sage, feat, b_gat, Whw, bhw, out, N);
}